// round 2
// baseline (speedup 1.0000x reference)
#include <cuda_runtime.h>
#include <math.h>

#define N_NODES 100000
#define N_EDGES 3200000
#define FIN 16
#define H 64

// ---------------- scratch (static device globals; 16B-aligned via float4) ----------------
__device__ int    g_deg [N_NODES];
__device__ float  g_dis [N_NODES];
__device__ int    g_ei64;                     // 1 if edge_index is int64, 0 if int32
__device__ float4 g_sx16[N_NODES * 4];        // layer-1 scaled features x*dis  (16 f/node)
__device__ float4 g_t16 [N_NODES * 4];        // layer-1 accumulator
__device__ float4 g_h   [N_NODES * 16];       // h1 after relu                   (64 f/node)
__device__ float4 g_sx64[N_NODES * 16];       // layer-2 scaled features (h1@W2)*dis
__device__ float4 g_t64 [N_NODES * 16];       // layer-2 accumulator

__device__ __forceinline__ int ld_idx(const void* ei, long long i, int is64) {
    return is64 ? (int)((const long long*)ei)[i] : ((const int*)ei)[i];
}

// ---------------- dtype probe: int64 values <2^31 have zero odd 32-bit words ----------------
__global__ void k_probe(const void* __restrict__ ei) {
    if (blockIdx.x == 0 && threadIdx.x == 0) {
        const int* w = (const int*)ei;
        int zeros = 0;
        for (int i = 1; i < 256; i += 2) zeros += (w[i] == 0);
        g_ei64 = (zeros >= 96) ? 1 : 0;       // 128 samples; int64 -> all ~128 zero
    }
}

// ---------------- degree ----------------
__global__ void k_zero_deg() {
    int i = blockIdx.x * blockDim.x + threadIdx.x;
    if (i < N_NODES) g_deg[i] = 0;
}

__global__ void k_deg(const void* __restrict__ ei) {
    int e = blockIdx.x * blockDim.x + threadIdx.x;
    if (e < N_EDGES) {
        int c = ld_idx(ei, (long long)N_EDGES + e, g_ei64);
        if ((unsigned)c < N_NODES) atomicAdd(&g_deg[c], 1);
    }
}

__global__ void k_dis() {
    int i = blockIdx.x * blockDim.x + threadIdx.x;
    if (i < N_NODES) g_dis[i] = rsqrtf((float)(g_deg[i] + 1));  // +1 self-loop
}

// ---------------- layer 1: scale x, init accumulator with self-loop ----------------
__global__ void k_s1(const float* __restrict__ x) {
    int t = blockIdx.x * blockDim.x + threadIdx.x;   // N*4 threads, float4 each
    if (t < N_NODES * 4) {
        int n = t >> 2;
        float d = g_dis[n];
        float4 v = ((const float4*)x)[t];
        v.x *= d; v.y *= d; v.z *= d; v.w *= d;
        g_sx16[t] = v;
        g_t16[t]  = v;   // self-loop contribution
    }
}

// ---------------- layer 1 edge pass: t16[col] += sx16[row] (16-wide) ----------------
__global__ void k_edge16(const void* __restrict__ ei) {
    int t = blockIdx.x * blockDim.x + threadIdx.x;   // E*4 threads
    if (t < N_EDGES * 4) {
        int e = t >> 2, j = t & 3;
        int is64 = g_ei64;
        int r = ld_idx(ei, e, is64);
        int c = ld_idx(ei, (long long)N_EDGES + e, is64);
        if ((unsigned)r >= N_NODES || (unsigned)c >= N_NODES) return;
        float4 v = g_sx16[r * 4 + j];
        float* p = (float*)g_t16 + c * FIN + j * 4;
        asm volatile("red.global.add.v4.f32 [%0], {%1,%2,%3,%4};"
                     :: "l"(p), "f"(v.x), "f"(v.y), "f"(v.z), "f"(v.w) : "memory");
    }
}

// ---------------- h1 = relu( (dis*t16) @ W1 + b1 ) ----------------
__global__ void k_h1(const float* __restrict__ W1, const float* __restrict__ b1) {
    __shared__ float sW[FIN * H];   // 4KB
    __shared__ float sA[4 * FIN];
    __shared__ float sb[H];
    int tid = threadIdx.x;                // 256 threads = 4 nodes x 64 outputs
    int n0 = blockIdx.x * 4;
    for (int k = tid; k < FIN * H; k += 256) sW[k] = W1[k];
    if (tid < H) sb[tid] = b1[tid];
    if (tid < 4 * FIN) {
        int nn = n0 + tid / FIN;
        if (nn < N_NODES) sA[tid] = g_dis[nn] * ((const float*)g_t16)[n0 * FIN + tid];
    }
    __syncthreads();
    int ln = tid >> 6, o = tid & 63;
    int n = n0 + ln;
    if (n < N_NODES) {
        float acc = sb[o];
        #pragma unroll
        for (int k = 0; k < FIN; k++) acc = fmaf(sA[ln * FIN + k], sW[k * H + o], acc);
        ((float*)g_h)[n * H + o] = fmaxf(acc, 0.0f);
    }
}

// ---------------- layer 2: sx64 = (h1 @ W2) * dis ; init t64 ----------------
__global__ void k_s2(const float* __restrict__ W2) {
    __shared__ float sW[H * H];    // 16KB
    __shared__ float sA[4 * H];
    int tid = threadIdx.x;                // 256 threads = 4 nodes x 64 outputs
    int n0 = blockIdx.x * 4;
    for (int k = tid; k < H * H; k += 256) sW[k] = W2[k];
    {
        int nn = n0 + tid / H;
        if (nn < N_NODES) sA[tid] = ((const float*)g_h)[n0 * H + tid];
    }
    __syncthreads();
    int ln = tid >> 6, o = tid & 63;
    int n = n0 + ln;
    if (n < N_NODES) {
        float acc = 0.0f;
        #pragma unroll
        for (int k = 0; k < H; k++) acc = fmaf(sA[ln * H + k], sW[k * H + o], acc);
        float v = acc * g_dis[n];
        ((float*)g_sx64)[n * H + o] = v;
        ((float*)g_t64)[n * H + o]  = v;   // self-loop contribution
    }
}

// ---------------- layer 2 edge pass: t64[col] += sx64[row] (64-wide) ----------------
__global__ void k_edge64(const void* __restrict__ ei) {
    long long t = (long long)blockIdx.x * blockDim.x + threadIdx.x;  // E*16 threads
    if (t < (long long)N_EDGES * 16) {
        int e = (int)(t >> 4), j = (int)(t & 15);
        int is64 = g_ei64;
        int r = ld_idx(ei, e, is64);
        int c = ld_idx(ei, (long long)N_EDGES + e, is64);
        if ((unsigned)r >= N_NODES || (unsigned)c >= N_NODES) return;
        float4 v = g_sx64[r * 16 + j];
        float* p = (float*)g_t64 + c * H + j * 4;
        asm volatile("red.global.add.v4.f32 [%0], {%1,%2,%3,%4};"
                     :: "l"(p), "f"(v.x), "f"(v.y), "f"(v.z), "f"(v.w) : "memory");
    }
}

// ---------------- final: relu(dis*t64 + b2), dot Wf, + bf, sigmoid ----------------
__global__ void k_fin(const float* __restrict__ b2, const float* __restrict__ Wf,
                      const float* __restrict__ bf, float* __restrict__ out) {
    int tid = blockIdx.x * blockDim.x + threadIdx.x;   // warp per node
    int n = tid >> 5, l = tid & 31;
    if (n >= N_NODES) return;
    float d = g_dis[n];
    const float* t64 = (const float*)g_t64;
    float v0 = fmaxf(fmaf(d, t64[n * H + l],      b2[l]),      0.0f);
    float v1 = fmaxf(fmaf(d, t64[n * H + 32 + l], b2[32 + l]), 0.0f);
    float s = v0 * Wf[l] + v1 * Wf[32 + l];
    #pragma unroll
    for (int off = 16; off > 0; off >>= 1) s += __shfl_down_sync(0xffffffffu, s, off);
    if (l == 0) out[n] = 1.0f / (1.0f + expf(-(s + bf[0])));
}

// ---------------- launch ----------------
extern "C" void kernel_launch(void* const* d_in, const int* in_sizes, int n_in,
                              void* d_out, int out_size) {
    // Size-based input resolution (robust to metadata ordering).
    int iX = 0, iEi = 1, iW1 = 2, iW2 = 4, iBf = 7;
    int p64[3] = {3, 5, 6}; int n64 = 0;
    bool any = false;
    for (int i = 0; i < n_in; i++) {
        int s = in_sizes[i];
        if (s == 2 * N_EDGES)           { iEi = i; any = true; }
        else if (s == N_NODES * FIN)    { iX = i; }
        else if (s == FIN * H)          { iW1 = i; }
        else if (s == H * H)            { iW2 = i; }
        else if (s == 1)                { iBf = i; }
        else if (s == H && n64 < 3)     { p64[n64++] = i; }
    }
    int iB1, iB2, iWf;
    if (n64 == 3 && p64[0] > iW2) { iWf = p64[0]; iB1 = p64[1]; iB2 = p64[2]; } // alphabetical-ish
    else                          { iB1 = p64[0]; iB2 = p64[1]; iWf = p64[2]; } // dict order
    (void)any;

    const float* x  = (const float*)d_in[iX];
    const void*  ei = d_in[iEi];
    const float* W1 = (const float*)d_in[iW1];
    const float* b1 = (const float*)d_in[iB1];
    const float* W2 = (const float*)d_in[iW2];
    const float* b2 = (const float*)d_in[iB2];
    const float* Wf = (const float*)d_in[iWf];
    const float* bf = (const float*)d_in[iBf];
    float* out = (float*)d_out;

    const int T = 256;
    k_probe   <<<1, 32>>>(ei);
    k_zero_deg<<<(N_NODES + T - 1) / T, T>>>();
    k_deg     <<<(N_EDGES + T - 1) / T, T>>>(ei);
    k_dis     <<<(N_NODES + T - 1) / T, T>>>();
    k_s1      <<<(N_NODES * 4 + T - 1) / T, T>>>(x);
    k_edge16  <<<(N_EDGES * 4 + T - 1) / T, T>>>(ei);
    k_h1      <<<(N_NODES + 3) / 4, T>>>(W1, b1);
    k_s2      <<<(N_NODES + 3) / 4, T>>>(W2);
    k_edge64  <<<(int)(((long long)N_EDGES * 16 + T - 1) / T), T>>>(ei);
    k_fin     <<<(N_NODES * 32 + T - 1) / T, T>>>(b2, Wf, bf, out);
}

// round 4
// speedup vs baseline: 1.4831x; 1.4831x over previous
#include <cuda_runtime.h>
#include <math.h>

#define N_NODES 100000
#define N_EDGES 3200000
#define FIN 16
#define H 64
#define NB_SCAN 196          // ceil(100000/512)

// ---------------- scratch (static device globals) ----------------
__device__ int    g_deg [N_NODES];
__device__ int    g_off [N_NODES + 1];
__device__ int    g_cur [N_NODES];
__device__ int    g_bsum[NB_SCAN];
__device__ int    g_boff[256];
__device__ int    g_total;
__device__ int    g_csr [N_EDGES];
__device__ float  g_dis [N_NODES];
__device__ int    g_ei64;
__device__ float4 g_sx16[N_NODES * 4];    // x * dis        (16 f/node)
__device__ float4 g_h   [N_NODES * 16];   // relu(agg1@W1+b1)
__device__ float4 g_sx64[N_NODES * 16];   // (h@W2) * dis   (64 f/node)

__device__ __forceinline__ int ld_idx(const void* ei, long long i, int is64) {
    return is64 ? (int)((const long long*)ei)[i] : ((const int*)ei)[i];
}

// ---------------- dtype probe ----------------
__global__ void k_probe(const void* __restrict__ ei) {
    if (threadIdx.x == 0) {
        const int* w = (const int*)ei;
        int zeros = 0;
        for (int i = 1; i < 256; i += 2) zeros += (w[i] == 0);
        g_ei64 = (zeros >= 96) ? 1 : 0;
    }
}

// ---------------- degree ----------------
__global__ void k_zero_deg() {
    int i = blockIdx.x * blockDim.x + threadIdx.x;
    if (i < N_NODES) g_deg[i] = 0;
}

__global__ void k_deg(const void* __restrict__ ei) {
    int e = blockIdx.x * blockDim.x + threadIdx.x;
    if (e < N_EDGES) {
        int c = ld_idx(ei, (long long)N_EDGES + e, g_ei64);
        if ((unsigned)c < N_NODES) atomicAdd(&g_deg[c], 1);
    }
}

__global__ void k_dis() {
    int i = blockIdx.x * blockDim.x + threadIdx.x;
    if (i < N_NODES) g_dis[i] = rsqrtf((float)(g_deg[i] + 1));
}

// ---------------- exclusive scan of deg -> off (3 kernels) ----------------
__global__ void k_scan_local() {        // 512 threads, NB_SCAN blocks
    __shared__ int s[512];
    int t = threadIdx.x, i = blockIdx.x * 512 + t;
    int v = (i < N_NODES) ? g_deg[i] : 0;
    s[t] = v; __syncthreads();
    #pragma unroll
    for (int d = 1; d < 512; d <<= 1) {
        int x = (t >= d) ? s[t - d] : 0;
        __syncthreads();
        if (t >= d) s[t] += x;
        __syncthreads();
    }
    if (i < N_NODES) g_off[i] = s[t] - v;          // exclusive within block
    if (t == 511) g_bsum[blockIdx.x] = s[511];
}

__global__ void k_scan_bsum() {         // 1 block, 256 threads
    __shared__ int s[256];
    int t = threadIdx.x;
    int v = (t < NB_SCAN) ? g_bsum[t] : 0;
    s[t] = v; __syncthreads();
    #pragma unroll
    for (int d = 1; d < 256; d <<= 1) {
        int x = (t >= d) ? s[t - d] : 0;
        __syncthreads();
        if (t >= d) s[t] += x;
        __syncthreads();
    }
    if (t < NB_SCAN) g_boff[t] = s[t] - v;
    if (t == NB_SCAN - 1) g_total = s[t];
}

__global__ void k_scan_add() {
    int i = blockIdx.x * blockDim.x + threadIdx.x;
    if (i < N_NODES) {
        int o = g_off[i] + g_boff[i >> 9];
        g_off[i] = o;
        g_cur[i] = o;
    }
    if (i == 0) g_off[N_NODES] = g_total;
}

// ---------------- scatter edges into CSR (by target) ----------------
__global__ void k_scatter(const void* __restrict__ ei) {
    int e = blockIdx.x * blockDim.x + threadIdx.x;
    if (e < N_EDGES) {
        int is64 = g_ei64;
        int r = ld_idx(ei, e, is64);
        int c = ld_idx(ei, (long long)N_EDGES + e, is64);
        if ((unsigned)r >= N_NODES || (unsigned)c >= N_NODES) return;
        int pos = atomicAdd(&g_cur[c], 1);
        g_csr[pos] = r;
    }
}

// ---------------- sx16 = x * dis ----------------
__global__ void k_s1(const float* __restrict__ x) {
    int t = blockIdx.x * blockDim.x + threadIdx.x;
    if (t < N_NODES * 4) {
        float d = g_dis[t >> 2];
        float4 v = ((const float4*)x)[t];
        v.x *= d; v.y *= d; v.z *= d; v.w *= d;
        g_sx16[t] = v;
    }
}

// ---------------- agg1 (16-wide CSR gather) fused with h1 = relu(agg@W1+b1) --------
__global__ void k_agg1(const float* __restrict__ W1, const float* __restrict__ b1) {
    __shared__ float sW[FIN * H];     // 4KB
    __shared__ float sb[H];
    __shared__ float sA[32 * FIN];    // 2KB: 32 nodes/block
    int tid = threadIdx.x;            // 128 threads: 4 per node
    int g = tid >> 2, j = tid & 3;
    int n = blockIdx.x * 32 + g;
    for (int k = tid; k < FIN * H; k += 128) sW[k] = W1[k];
    if (tid < H) sb[tid] = b1[tid];

    if (n < N_NODES) {
        float4 acc = g_sx16[n * 4 + j];           // self-loop
        int i = g_off[n], end = g_off[n + 1];
        for (; i + 4 <= end; i += 4) {
            int r0 = g_csr[i], r1 = g_csr[i+1], r2 = g_csr[i+2], r3 = g_csr[i+3];
            float4 v0 = g_sx16[r0*4+j], v1 = g_sx16[r1*4+j];
            float4 v2 = g_sx16[r2*4+j], v3 = g_sx16[r3*4+j];
            acc.x += v0.x+v1.x+v2.x+v3.x; acc.y += v0.y+v1.y+v2.y+v3.y;
            acc.z += v0.z+v1.z+v2.z+v3.z; acc.w += v0.w+v1.w+v2.w+v3.w;
        }
        for (; i < end; i++) {
            float4 v = g_sx16[g_csr[i]*4+j];
            acc.x += v.x; acc.y += v.y; acc.z += v.z; acc.w += v.w;
        }
        float d = g_dis[n];
        sA[g*FIN + j*4+0] = acc.x*d; sA[g*FIN + j*4+1] = acc.y*d;
        sA[g*FIN + j*4+2] = acc.z*d; sA[g*FIN + j*4+3] = acc.w*d;
    }
    __syncthreads();
    if (n < N_NODES) {
        float oo[16];                             // outputs j*16 .. j*16+15
        #pragma unroll
        for (int q = 0; q < 16; q++) {
            int o = j * 16 + q;
            float acc2 = sb[o];
            #pragma unroll
            for (int k = 0; k < FIN; k++) acc2 = fmaf(sA[g*FIN+k], sW[k*H+o], acc2);
            oo[q] = fmaxf(acc2, 0.0f);
        }
        float4* dst = &g_h[n * 16 + j * 4];
        #pragma unroll
        for (int q = 0; q < 4; q++)
            dst[q] = make_float4(oo[q*4+0], oo[q*4+1], oo[q*4+2], oo[q*4+3]);
    }
}

// ---------------- sx64 = (h @ W2) * dis ----------------
__global__ void k_s2(const float* __restrict__ W2) {
    __shared__ float sW[H * H];    // 16KB
    __shared__ float sA[4 * H];
    int tid = threadIdx.x;         // 256 threads = 4 nodes x 64 outputs
    int n0 = blockIdx.x * 4;
    for (int k = tid; k < H * H; k += 256) sW[k] = W2[k];
    {
        int nn = n0 + tid / H;
        if (nn < N_NODES) sA[tid] = ((const float*)g_h)[n0 * H + tid];
    }
    __syncthreads();
    int ln = tid >> 6, o = tid & 63;
    int n = n0 + ln;
    if (n < N_NODES) {
        float acc = 0.0f;
        #pragma unroll
        for (int k = 0; k < H; k++) acc = fmaf(sA[ln * H + k], sW[k * H + o], acc);
        ((float*)g_sx64)[n * H + o] = acc * g_dis[n];
    }
}

// ---------------- agg2 (64-wide CSR gather) fused with final scorer ----------------
__global__ void k_agg2_fin(const float* __restrict__ b2, const float* __restrict__ Wf,
                           const float* __restrict__ bf, float* __restrict__ out) {
    int tid = blockIdx.x * blockDim.x + threadIdx.x;   // 16 threads per node
    int n = tid >> 4, j = tid & 15;
    if (n >= N_NODES) return;

    float4 acc = g_sx64[n * 16 + j];                   // self-loop
    int i = g_off[n], end = g_off[n + 1];
    for (; i + 4 <= end; i += 4) {
        int r0 = g_csr[i], r1 = g_csr[i+1], r2 = g_csr[i+2], r3 = g_csr[i+3];
        float4 v0 = g_sx64[r0*16+j], v1 = g_sx64[r1*16+j];
        float4 v2 = g_sx64[r2*16+j], v3 = g_sx64[r3*16+j];
        acc.x += v0.x+v1.x+v2.x+v3.x; acc.y += v0.y+v1.y+v2.y+v3.y;
        acc.z += v0.z+v1.z+v2.z+v3.z; acc.w += v0.w+v1.w+v2.w+v3.w;
    }
    for (; i < end; i++) {
        float4 v = g_sx64[g_csr[i]*16+j];
        acc.x += v.x; acc.y += v.y; acc.z += v.z; acc.w += v.w;
    }
    float d = g_dis[n];
    float4 b = ((const float4*)b2)[j];
    float4 w = ((const float4*)Wf)[j];
    float s = fmaxf(fmaf(acc.x, d, b.x), 0.0f) * w.x
            + fmaxf(fmaf(acc.y, d, b.y), 0.0f) * w.y
            + fmaxf(fmaf(acc.z, d, b.z), 0.0f) * w.z
            + fmaxf(fmaf(acc.w, d, b.w), 0.0f) * w.w;
    #pragma unroll
    for (int off = 8; off > 0; off >>= 1) s += __shfl_down_sync(0xffffffffu, s, off, 16);
    if (j == 0) out[n] = 1.0f / (1.0f + expf(-(s + bf[0])));
}

// ---------------- launch ----------------
extern "C" void kernel_launch(void* const* d_in, const int* in_sizes, int n_in,
                              void* d_out, int out_size) {
    int iX = 0, iEi = 1, iW1 = 2, iW2 = 4, iBf = 7;
    int p64[3] = {3, 5, 6}; int n64 = 0;
    for (int i = 0; i < n_in; i++) {
        int s = in_sizes[i];
        if (s == 2 * N_EDGES)        iEi = i;
        else if (s == N_NODES * FIN) iX = i;
        else if (s == FIN * H)       iW1 = i;
        else if (s == H * H)         iW2 = i;
        else if (s == 1)             iBf = i;
        else if (s == H && n64 < 3)  p64[n64++] = i;
    }
    int iB1, iB2, iWf;
    if (n64 == 3 && p64[0] > iW2) { iWf = p64[0]; iB1 = p64[1]; iB2 = p64[2]; }
    else                          { iB1 = p64[0]; iB2 = p64[1]; iWf = p64[2]; }

    const float* x  = (const float*)d_in[iX];
    const void*  ei = d_in[iEi];
    const float* W1 = (const float*)d_in[iW1];
    const float* b1 = (const float*)d_in[iB1];
    const float* W2 = (const float*)d_in[iW2];
    const float* b2 = (const float*)d_in[iB2];
    const float* Wf = (const float*)d_in[iWf];
    const float* bf = (const float*)d_in[iBf];
    float* out = (float*)d_out;

    const int T = 256;
    k_probe     <<<1, 32>>>(ei);
    k_zero_deg  <<<(N_NODES + T - 1) / T, T>>>();
    k_deg       <<<(N_EDGES + T - 1) / T, T>>>(ei);
    k_dis       <<<(N_NODES + T - 1) / T, T>>>();
    k_scan_local<<<NB_SCAN, 512>>>();
    k_scan_bsum <<<1, 256>>>();
    k_scan_add  <<<(N_NODES + T - 1) / T, T>>>();
    k_scatter   <<<(N_EDGES + T - 1) / T, T>>>(ei);
    k_s1        <<<(N_NODES * 4 + T - 1) / T, T>>>(x);
    k_agg1      <<<(N_NODES + 31) / 32, 128>>>(W1, b1);
    k_s2        <<<(N_NODES + 3) / 4, T>>>(W2);
    k_agg2_fin  <<<(N_NODES * 16 + T - 1) / T, T>>>(b2, Wf, bf, out);
}

// round 6
// speedup vs baseline: 1.6745x; 1.1291x over previous
#include <cuda_runtime.h>
#include <cuda_fp16.h>
#include <math.h>

#define N_NODES 100000
#define N_EDGES 3200000
#define FIN 16
#define H 64
#define NB_SCAN 196          // ceil(100000/512)

// ---------------- scratch (static device globals) ----------------
__device__ int     g_deg [N_NODES];
__device__ int     g_off [N_NODES + 1];
__device__ int     g_cur [N_NODES];
__device__ int     g_bsum[NB_SCAN];
__device__ int     g_boff[256];
__device__ int     g_total;
__device__ int     g_csr [N_EDGES];
__device__ float   g_dis [N_NODES];
__device__ int     g_ei64;
__device__ float4  g_sx16 [N_NODES * 4];    // x * dis (16 f32/node)
__device__ __half2 g_sx64h[N_NODES * 32];   // (h@W2)*dis (64 fp16/node, 128B rows)

__device__ __forceinline__ int ld_idx(const void* ei, long long i, int is64) {
    return is64 ? (int)((const long long*)ei)[i] : ((const int*)ei)[i];
}

// ---------------- init: dtype probe + zero degree ----------------
__global__ void k_init(const void* __restrict__ ei) {
    int i = blockIdx.x * blockDim.x + threadIdx.x;
    if (i < N_NODES) g_deg[i] = 0;
    if (i == 0) {
        const int* w = (const int*)ei;
        int zeros = 0;
        for (int q = 1; q < 256; q += 2) zeros += (w[q] == 0);
        g_ei64 = (zeros >= 96) ? 1 : 0;
    }
}

// ---------------- degree ----------------
__global__ void k_deg(const void* __restrict__ ei) {
    int e = blockIdx.x * blockDim.x + threadIdx.x;
    if (e < N_EDGES) {
        int c = ld_idx(ei, (long long)N_EDGES + e, g_ei64);
        if ((unsigned)c < N_NODES) atomicAdd(&g_deg[c], 1);
    }
}

// ---------------- scan part 1 (+ dis) ----------------
__global__ void k_scan_local() {        // 512 threads, NB_SCAN blocks
    __shared__ int s[512];
    int t = threadIdx.x, i = blockIdx.x * 512 + t;
    int v = (i < N_NODES) ? g_deg[i] : 0;
    if (i < N_NODES) g_dis[i] = rsqrtf((float)(v + 1));   // +1 self-loop
    s[t] = v; __syncthreads();
    #pragma unroll
    for (int d = 1; d < 512; d <<= 1) {
        int x = (t >= d) ? s[t - d] : 0;
        __syncthreads();
        if (t >= d) s[t] += x;
        __syncthreads();
    }
    if (i < N_NODES) g_off[i] = s[t] - v;
    if (t == 511) g_bsum[blockIdx.x] = s[511];
}

__global__ void k_scan_bsum() {         // 1 block, 256 threads
    __shared__ int s[256];
    int t = threadIdx.x;
    int v = (t < NB_SCAN) ? g_bsum[t] : 0;
    s[t] = v; __syncthreads();
    #pragma unroll
    for (int d = 1; d < 256; d <<= 1) {
        int x = (t >= d) ? s[t - d] : 0;
        __syncthreads();
        if (t >= d) s[t] += x;
        __syncthreads();
    }
    if (t < NB_SCAN) g_boff[t] = s[t] - v;
    if (t == NB_SCAN - 1) g_total = s[t];
}

// ---------------- scan finalize + sx16 = x*dis ----------------
__global__ void k_scan_add_s1(const float* __restrict__ x) {
    int t = blockIdx.x * blockDim.x + threadIdx.x;   // N*4 threads
    if (t < N_NODES) {
        int o = g_off[t] + g_boff[t >> 9];
        g_off[t] = o;
        g_cur[t] = o;
        if (t == 0) g_off[N_NODES] = g_total;
    }
    if (t < N_NODES * 4) {
        float d = g_dis[t >> 2];
        float4 v = ((const float4*)x)[t];
        v.x *= d; v.y *= d; v.z *= d; v.w *= d;
        g_sx16[t] = v;
    }
}

// ---------------- scatter edges into CSR (by target) ----------------
__global__ void k_scatter(const void* __restrict__ ei) {
    int e = blockIdx.x * blockDim.x + threadIdx.x;
    if (e < N_EDGES) {
        int is64 = g_ei64;
        int r = ld_idx(ei, e, is64);
        int c = ld_idx(ei, (long long)N_EDGES + e, is64);
        if ((unsigned)r >= N_NODES || (unsigned)c >= N_NODES) return;
        int pos = atomicAdd(&g_cur[c], 1);
        g_csr[pos] = r;
    }
}

// ---- agg1 (16-wide gather) + h=relu(.@W1+b1) + sx64=(h@W2)*dis -> fp16, fused ----
#define ASTR 17
#define HSTR 65
__global__ void __launch_bounds__(128) k_agg1s2(const float* __restrict__ W1,
                                                const float* __restrict__ b1,
                                                const float* __restrict__ W2) {
    __shared__ float sW1[FIN * H];      // 4KB
    __shared__ float sW2[H * H];        // 16KB
    __shared__ float sb1[H];
    __shared__ float sA[32 * ASTR];     // padded: conflict-free
    __shared__ float sH[32 * HSTR];     // padded: conflict-free
    __shared__ float sdis[32];
    int tid = threadIdx.x;              // 128 threads: 4 per node, 32 nodes
    int g = tid >> 2, j = tid & 3;
    int n = blockIdx.x * 32 + g;
    for (int k = tid; k < FIN * H; k += 128) sW1[k] = W1[k];
    for (int k = tid; k < H * H; k += 128) sW2[k] = W2[k];
    if (tid < H) sb1[tid] = b1[tid];
    if (tid < 32) sdis[tid] = (blockIdx.x * 32 + tid < N_NODES) ? g_dis[blockIdx.x * 32 + tid] : 0.0f;

    // phase 1: gather-aggregate 16-wide
    if (n < N_NODES) {
        float4 acc = g_sx16[n * 4 + j];           // self-loop
        int i = g_off[n], end = g_off[n + 1];
        for (; i + 4 <= end; i += 4) {
            int r0 = g_csr[i], r1 = g_csr[i+1], r2 = g_csr[i+2], r3 = g_csr[i+3];
            float4 v0 = g_sx16[r0*4+j], v1 = g_sx16[r1*4+j];
            float4 v2 = g_sx16[r2*4+j], v3 = g_sx16[r3*4+j];
            acc.x += v0.x+v1.x+v2.x+v3.x; acc.y += v0.y+v1.y+v2.y+v3.y;
            acc.z += v0.z+v1.z+v2.z+v3.z; acc.w += v0.w+v1.w+v2.w+v3.w;
        }
        for (; i < end; i++) {
            float4 v = g_sx16[g_csr[i]*4+j];
            acc.x += v.x; acc.y += v.y; acc.z += v.z; acc.w += v.w;
        }
        float d = sdis[g];
        sA[g*ASTR + j*4+0] = acc.x*d; sA[g*ASTR + j*4+1] = acc.y*d;
        sA[g*ASTR + j*4+2] = acc.z*d; sA[g*ASTR + j*4+3] = acc.w*d;
    }
    __syncthreads();
    // phase 2: h = relu(sA @ W1 + b1), 16 outputs per thread
    if (n < N_NODES) {
        #pragma unroll
        for (int q = 0; q < 16; q++) {
            int o = j * 16 + q;
            float acc2 = sb1[o];
            #pragma unroll
            for (int k = 0; k < FIN; k++) acc2 = fmaf(sA[g*ASTR+k], sW1[k*H+o], acc2);
            sH[g*HSTR + o] = fmaxf(acc2, 0.0f);
        }
    }
    __syncthreads();
    // phase 3: sx64 = (h @ W2) * dis -> fp16, 16 outputs per thread
    if (n < N_NODES) {
        float d = sdis[g];
        float oo[16];
        #pragma unroll
        for (int q = 0; q < 16; q++) {
            int o = j * 16 + q;
            float acc3 = 0.0f;
            #pragma unroll
            for (int k = 0; k < H; k++) acc3 = fmaf(sH[g*HSTR+k], sW2[k*H+o], acc3);
            oo[q] = acc3 * d;
        }
        __half2 hh[8];
        #pragma unroll
        for (int q = 0; q < 8; q++) hh[q] = __floats2half2_rn(oo[2*q], oo[2*q+1]);
        uint4* dst = (uint4*)&g_sx64h[n * 32 + j * 8];   // 32B, 16B-aligned
        dst[0] = ((uint4*)hh)[0];
        dst[1] = ((uint4*)hh)[1];
    }
}

// ---------------- agg2 (64-wide fp16 gather) fused with final scorer ----------------
__global__ void __launch_bounds__(128) k_agg2_fin(const float* __restrict__ b2,
                                                  const float* __restrict__ Wf,
                                                  const float* __restrict__ bf,
                                                  float* __restrict__ out) {
    int tid = blockIdx.x * blockDim.x + threadIdx.x;   // 16 threads per node
    int n = tid >> 4, j = tid & 15;
    if (n >= N_NODES) return;
    const uint2* sx = (const uint2*)g_sx64h;           // 16 uint2 per 128B row

    float4 acc = make_float4(0.f, 0.f, 0.f, 0.f);
    {
        uint2 u = sx[n * 16 + j];                      // self-loop
        float2 a = __half22float2(*(__half2*)&u.x), b = __half22float2(*(__half2*)&u.y);
        acc.x = a.x; acc.y = a.y; acc.z = b.x; acc.w = b.y;
    }
    int i = g_off[n], end = g_off[n + 1];
    for (; i + 4 <= end; i += 4) {
        int r0 = g_csr[i], r1 = g_csr[i+1], r2 = g_csr[i+2], r3 = g_csr[i+3];
        uint2 u0 = sx[r0*16+j], u1 = sx[r1*16+j], u2 = sx[r2*16+j], u3 = sx[r3*16+j];
        float2 a0 = __half22float2(*(__half2*)&u0.x), b0 = __half22float2(*(__half2*)&u0.y);
        float2 a1 = __half22float2(*(__half2*)&u1.x), b1 = __half22float2(*(__half2*)&u1.y);
        float2 a2 = __half22float2(*(__half2*)&u2.x), b2v = __half22float2(*(__half2*)&u2.y);
        float2 a3 = __half22float2(*(__half2*)&u3.x), b3 = __half22float2(*(__half2*)&u3.y);
        acc.x += a0.x+a1.x+a2.x+a3.x; acc.y += a0.y+a1.y+a2.y+a3.y;
        acc.z += b0.x+b1.x+b2v.x+b3.x; acc.w += b0.y+b1.y+b2v.y+b3.y;
    }
    for (; i < end; i++) {
        uint2 u = sx[g_csr[i]*16+j];
        float2 a = __half22float2(*(__half2*)&u.x), b = __half22float2(*(__half2*)&u.y);
        acc.x += a.x; acc.y += a.y; acc.z += b.x; acc.w += b.y;
    }
    float d = g_dis[n];
    float4 b = ((const float4*)b2)[j];
    float4 w = ((const float4*)Wf)[j];
    float s = fmaxf(fmaf(acc.x, d, b.x), 0.0f) * w.x
            + fmaxf(fmaf(acc.y, d, b.y), 0.0f) * w.y
            + fmaxf(fmaf(acc.z, d, b.z), 0.0f) * w.z
            + fmaxf(fmaf(acc.w, d, b.w), 0.0f) * w.w;
    #pragma unroll
    for (int off = 8; off > 0; off >>= 1) s += __shfl_down_sync(0xffffffffu, s, off, 16);
    if (j == 0) out[n] = 1.0f / (1.0f + expf(-(s + bf[0])));
}

// ---------------- launch ----------------
extern "C" void kernel_launch(void* const* d_in, const int* in_sizes, int n_in,
                              void* d_out, int out_size) {
    int iX = 0, iEi = 1, iW1 = 2, iW2 = 4, iBf = 7;
    int p64[3] = {3, 5, 6}; int n64 = 0;
    for (int i = 0; i < n_in; i++) {
        int s = in_sizes[i];
        if (s == 2 * N_EDGES)        iEi = i;
        else if (s == N_NODES * FIN) iX = i;
        else if (s == FIN * H)       iW1 = i;
        else if (s == H * H)         iW2 = i;
        else if (s == 1)             iBf = i;
        else if (s == H && n64 < 3)  p64[n64++] = i;
    }
    int iB1, iB2, iWf;
    if (n64 == 3 && p64[0] > iW2) { iWf = p64[0]; iB1 = p64[1]; iB2 = p64[2]; }
    else                          { iB1 = p64[0]; iB2 = p64[1]; iWf = p64[2]; }

    const float* x  = (const float*)d_in[iX];
    const void*  ei = d_in[iEi];
    const float* W1 = (const float*)d_in[iW1];
    const float* b1 = (const float*)d_in[iB1];
    const float* W2 = (const float*)d_in[iW2];
    const float* b2 = (const float*)d_in[iB2];
    const float* Wf = (const float*)d_in[iWf];
    const float* bf = (const float*)d_in[iBf];
    float* out = (float*)d_out;

    const int T = 256;
    k_init       <<<(N_NODES + T - 1) / T, T>>>(ei);
    k_deg        <<<(N_EDGES + T - 1) / T, T>>>(ei);
    k_scan_local <<<NB_SCAN, 512>>>();
    k_scan_bsum  <<<1, 256>>>();
    k_scan_add_s1<<<(N_NODES * 4 + T - 1) / T, T>>>(x);
    k_scatter    <<<(N_EDGES + T - 1) / T, T>>>(ei);
    k_agg1s2     <<<(N_NODES + 31) / 32, 128>>>(W1, b1, W2);
    k_agg2_fin   <<<(N_NODES * 16 + 127) / 128, 128>>>(b2, Wf, bf, out);
}

// round 7
// speedup vs baseline: 1.6749x; 1.0002x over previous
#include <cuda_runtime.h>
#include <cuda_fp16.h>
#include <math.h>

#define N_NODES 100000
#define N_EDGES 3200000
#define FIN 16
#define H 64
#define NB_SCAN 196          // ceil(100000/512)

// ---------------- scratch (static device globals) ----------------
__device__ int     g_deg  [N_NODES];
__device__ int     g_off  [N_NODES];
__device__ int     g_cur  [N_NODES];
__device__ int     g_alloc;
__device__ int     g_csr  [N_EDGES];
__device__ float   g_dis  [N_NODES];
__device__ int     g_ei64;
__device__ __half2 g_sx16h[N_NODES * 8];    // x * dis     (16 fp16/node, 32B rows)
__device__ __half2 g_sx64h[N_NODES * 32];   // (h@W2)*dis  (64 fp16/node, 128B rows)

__device__ __forceinline__ int ld_idx(const void* ei, long long i, int is64) {
    return is64 ? (int)((const long long*)ei)[i] : ((const int*)ei)[i];
}

// ---------------- init: dtype probe + zero degree + zero allocator ----------------
__global__ void k_init(const void* __restrict__ ei) {
    int i = blockIdx.x * blockDim.x + threadIdx.x;
    if (i < N_NODES) g_deg[i] = 0;
    if (i == 0) {
        g_alloc = 0;
        const int* w = (const int*)ei;
        int zeros = 0;
        for (int q = 1; q < 256; q += 2) zeros += (w[q] == 0);
        g_ei64 = (zeros >= 96) ? 1 : 0;
    }
}

// ---------------- degree ----------------
__global__ void k_deg(const void* __restrict__ ei) {
    int e = blockIdx.x * blockDim.x + threadIdx.x;
    if (e < N_EDGES) {
        int c = ld_idx(ei, (long long)N_EDGES + e, g_ei64);
        if ((unsigned)c < N_NODES) atomicAdd(&g_deg[c], 1);
    }
}

// ------ single-pass scan (atomic block allocation) + dis + sx16 fp16 conversion ------
__global__ void __launch_bounds__(512) k_scan(const float* __restrict__ x) {
    __shared__ int   s[512];
    __shared__ float sd[512];
    __shared__ int   sbase;
    int t = threadIdx.x, i = blockIdx.x * 512 + t;
    int v = (i < N_NODES) ? g_deg[i] : 0;
    float d = rsqrtf((float)(v + 1));              // +1 self-loop
    if (i < N_NODES) g_dis[i] = d;
    sd[t] = d;
    s[t] = v; __syncthreads();
    #pragma unroll
    for (int dd = 1; dd < 512; dd <<= 1) {
        int xx = (t >= dd) ? s[t - dd] : 0;
        __syncthreads();
        if (t >= dd) s[t] += xx;
        __syncthreads();
    }
    if (t == 511) sbase = atomicAdd(&g_alloc, s[511]);
    __syncthreads();
    if (i < N_NODES) {
        int o = sbase + s[t] - v;                  // exclusive local + block base
        g_off[i] = o;
        g_cur[i] = o;
    }
    // fused: sx16 = fp16(x * dis), coalesced float4 reads
    const float4* xv = (const float4*)x;
    uint2* dst = (uint2*)g_sx16h;                  // 1 uint2 = 4 fp16
    #pragma unroll
    for (int w = 0; w < 4; w++) {
        int t2 = blockIdx.x * 2048 + w * 512 + t;
        if (t2 < N_NODES * 4) {
            float dd = sd[(w * 512 + t) >> 2];
            float4 vx = xv[t2];
            __half2 h0 = __floats2half2_rn(vx.x * dd, vx.y * dd);
            __half2 h1 = __floats2half2_rn(vx.z * dd, vx.w * dd);
            uint2 u;
            u.x = *(unsigned*)&h0; u.y = *(unsigned*)&h1;
            dst[t2] = u;
        }
    }
}

// ---------------- scatter edges into CSR (by target) ----------------
__global__ void k_scatter(const void* __restrict__ ei) {
    int e = blockIdx.x * blockDim.x + threadIdx.x;
    if (e < N_EDGES) {
        int is64 = g_ei64;
        int r = ld_idx(ei, e, is64);
        int c = ld_idx(ei, (long long)N_EDGES + e, is64);
        if ((unsigned)r >= N_NODES || (unsigned)c >= N_NODES) return;
        int pos = atomicAdd(&g_cur[c], 1);
        g_csr[pos] = r;
    }
}

// ---- agg1 (16-wide fp16 gather) + h=relu(.@W1+b1) + sx64=(h@W2)*dis -> fp16 ----
#define ASTR 17
#define HSTR 65
__device__ __forceinline__ void acc_h4(float4& a, uint2 u) {
    float2 p = __half22float2(*(__half2*)&u.x), q = __half22float2(*(__half2*)&u.y);
    a.x += p.x; a.y += p.y; a.z += q.x; a.w += q.y;
}
__global__ void __launch_bounds__(128) k_agg1s2(const float* __restrict__ W1,
                                                const float* __restrict__ b1,
                                                const float* __restrict__ W2) {
    __shared__ float sW1[FIN * H];      // 4KB
    __shared__ float sW2[H * H];        // 16KB
    __shared__ float sb1[H];
    __shared__ float sA[32 * ASTR];
    __shared__ float sH[32 * HSTR];
    __shared__ float sdis[32];
    int tid = threadIdx.x;              // 128 threads: 4 per node, 32 nodes
    int g = tid >> 2, j = tid & 3;
    int n = blockIdx.x * 32 + g;
    for (int k = tid; k < FIN * H; k += 128) sW1[k] = W1[k];
    for (int k = tid; k < H * H; k += 128) sW2[k] = W2[k];
    if (tid < H) sb1[tid] = b1[tid];
    if (tid < 32) sdis[tid] = (blockIdx.x * 32 + tid < N_NODES) ? g_dis[blockIdx.x * 32 + tid] : 0.0f;

    const uint2* sx = (const uint2*)g_sx16h;       // 4 uint2 per 32B row
    // phase 1: gather-aggregate 16-wide (fp16 -> fp32 acc)
    if (n < N_NODES) {
        float4 acc = make_float4(0.f, 0.f, 0.f, 0.f);
        acc_h4(acc, sx[n * 4 + j]);                // self-loop
        int i = g_off[n], end = i + g_deg[n];
        for (; i + 4 <= end; i += 4) {
            int r0 = g_csr[i], r1 = g_csr[i+1], r2 = g_csr[i+2], r3 = g_csr[i+3];
            uint2 u0 = sx[r0*4+j], u1 = sx[r1*4+j], u2 = sx[r2*4+j], u3 = sx[r3*4+j];
            acc_h4(acc, u0); acc_h4(acc, u1); acc_h4(acc, u2); acc_h4(acc, u3);
        }
        for (; i < end; i++) acc_h4(acc, sx[g_csr[i]*4+j]);
        float d = sdis[g];
        sA[g*ASTR + j*4+0] = acc.x*d; sA[g*ASTR + j*4+1] = acc.y*d;
        sA[g*ASTR + j*4+2] = acc.z*d; sA[g*ASTR + j*4+3] = acc.w*d;
    }
    __syncthreads();
    // phase 2: h = relu(sA @ W1 + b1)
    if (n < N_NODES) {
        #pragma unroll
        for (int q = 0; q < 16; q++) {
            int o = j * 16 + q;
            float acc2 = sb1[o];
            #pragma unroll
            for (int k = 0; k < FIN; k++) acc2 = fmaf(sA[g*ASTR+k], sW1[k*H+o], acc2);
            sH[g*HSTR + o] = fmaxf(acc2, 0.0f);
        }
    }
    __syncthreads();
    // phase 3: sx64 = (h @ W2) * dis -> fp16
    if (n < N_NODES) {
        float d = sdis[g];
        float oo[16];
        #pragma unroll
        for (int q = 0; q < 16; q++) {
            int o = j * 16 + q;
            float acc3 = 0.0f;
            #pragma unroll
            for (int k = 0; k < H; k++) acc3 = fmaf(sH[g*HSTR+k], sW2[k*H+o], acc3);
            oo[q] = acc3 * d;
        }
        __half2 hh[8];
        #pragma unroll
        for (int q = 0; q < 8; q++) hh[q] = __floats2half2_rn(oo[2*q], oo[2*q+1]);
        uint4* dst = (uint4*)&g_sx64h[n * 32 + j * 8];
        dst[0] = ((uint4*)hh)[0];
        dst[1] = ((uint4*)hh)[1];
    }
}

// ---------------- agg2 (64-wide fp16 gather, unroll 8) + final scorer ----------------
__global__ void __launch_bounds__(128) k_agg2_fin(const float* __restrict__ b2,
                                                  const float* __restrict__ Wf,
                                                  const float* __restrict__ bf,
                                                  float* __restrict__ out) {
    int tid = blockIdx.x * blockDim.x + threadIdx.x;   // 16 threads per node
    int n = tid >> 4, j = tid & 15;
    if (n >= N_NODES) return;
    const uint2* sx = (const uint2*)g_sx64h;           // 16 uint2 per 128B row

    float4 acc = make_float4(0.f, 0.f, 0.f, 0.f);
    acc_h4(acc, sx[n * 16 + j]);                       // self-loop
    int i = g_off[n], end = i + g_deg[n];
    for (; i + 8 <= end; i += 8) {
        uint2 u0 = sx[g_csr[i+0]*16+j], u1 = sx[g_csr[i+1]*16+j];
        uint2 u2 = sx[g_csr[i+2]*16+j], u3 = sx[g_csr[i+3]*16+j];
        uint2 u4 = sx[g_csr[i+4]*16+j], u5 = sx[g_csr[i+5]*16+j];
        uint2 u6 = sx[g_csr[i+6]*16+j], u7 = sx[g_csr[i+7]*16+j];
        acc_h4(acc, u0); acc_h4(acc, u1); acc_h4(acc, u2); acc_h4(acc, u3);
        acc_h4(acc, u4); acc_h4(acc, u5); acc_h4(acc, u6); acc_h4(acc, u7);
    }
    for (; i < end; i++) acc_h4(acc, sx[g_csr[i]*16+j]);

    float d = g_dis[n];
    float4 b = ((const float4*)b2)[j];
    float4 w = ((const float4*)Wf)[j];
    float s = fmaxf(fmaf(acc.x, d, b.x), 0.0f) * w.x
            + fmaxf(fmaf(acc.y, d, b.y), 0.0f) * w.y
            + fmaxf(fmaf(acc.z, d, b.z), 0.0f) * w.z
            + fmaxf(fmaf(acc.w, d, b.w), 0.0f) * w.w;
    #pragma unroll
    for (int off = 8; off > 0; off >>= 1) s += __shfl_down_sync(0xffffffffu, s, off, 16);
    if (j == 0) out[n] = 1.0f / (1.0f + expf(-(s + bf[0])));
}

// ---------------- launch ----------------
extern "C" void kernel_launch(void* const* d_in, const int* in_sizes, int n_in,
                              void* d_out, int out_size) {
    int iX = 0, iEi = 1, iW1 = 2, iW2 = 4, iBf = 7;
    int p64[3] = {3, 5, 6}; int n64 = 0;
    for (int i = 0; i < n_in; i++) {
        int s = in_sizes[i];
        if (s == 2 * N_EDGES)        iEi = i;
        else if (s == N_NODES * FIN) iX = i;
        else if (s == FIN * H)       iW1 = i;
        else if (s == H * H)         iW2 = i;
        else if (s == 1)             iBf = i;
        else if (s == H && n64 < 3)  p64[n64++] = i;
    }
    int iB1, iB2, iWf;
    if (n64 == 3 && p64[0] > iW2) { iWf = p64[0]; iB1 = p64[1]; iB2 = p64[2]; }
    else                          { iB1 = p64[0]; iB2 = p64[1]; iWf = p64[2]; }

    const float* x  = (const float*)d_in[iX];
    const void*  ei = d_in[iEi];
    const float* W1 = (const float*)d_in[iW1];
    const float* b1 = (const float*)d_in[iB1];
    const float* W2 = (const float*)d_in[iW2];
    const float* b2 = (const float*)d_in[iB2];
    const float* Wf = (const float*)d_in[iWf];
    const float* bf = (const float*)d_in[iBf];
    float* out = (float*)d_out;

    const int T = 256;
    k_init    <<<(N_NODES + T - 1) / T, T>>>(ei);
    k_deg     <<<(N_EDGES + T - 1) / T, T>>>(ei);
    k_scan    <<<NB_SCAN, 512>>>(x);
    k_scatter <<<(N_EDGES + T - 1) / T, T>>>(ei);
    k_agg1s2  <<<(N_NODES + 31) / 32, 128>>>(W1, b1, W2);
    k_agg2_fin<<<(N_NODES * 16 + 127) / 128, 128>>>(b2, Wf, bf, out);
}